// round 9
// baseline (speedup 1.0000x reference)
#include <cuda_runtime.h>
#include <cuda.h>
#include <cstdint>

// FWHT n=1024 over x[64,1024,512] f32, single pass, TMA-pipelined.
//
// R9 = R8 (256 threads, 3 x 64KB buffers, persistent 1 CTA/SM, prefetch
// depth 2) with the t+2 prefetch MOVED to after the tile-t store issue,
// gated by wait_group 1 (waits only on the t-1 store, which has had a
// full iteration to drain) instead of wait_group 0 at the iteration top
// (which blocked on the just-issued t-1 store every iteration).
//
// n = 32*a + b. Phase A: FWHT_32 over a (rows 32a+jt); swizzled smem
// exchange; Phase B: FWHT_32 over b (rows jt*32+b).

#define FW_N 1024
#define FW_D 512
#define FW_TW 16                          // tile width in floats (64 B)
#define FW_THREADS 256
#define FW_NTILES (64 * (FW_D / FW_TW))   // 2048
#define FW_TILE_BYTES (FW_N * FW_TW * 4)  // 65536
#define FW_NBUF 3
#define FW_MBAR_OFF (FW_NBUF * FW_TILE_BYTES)
#define FW_SMEM_BYTES (FW_MBAR_OFF + 64)

typedef unsigned long long u64t;

// packed butterfly on a float2-as-u64: (a,b) -> (a+b, a-b)
__device__ __forceinline__ void bfly(u64t& a, u64t& b) {
    u64t s, d;
    asm("add.rn.f32x2 %0, %2, %3;\n\t"
        "sub.rn.f32x2 %1, %2, %3;"
        : "=l"(s), "=l"(d)
        : "l"(a), "l"(b));
    a = s; b = d;
}

__device__ __forceinline__ void mbar_init(uint32_t mbar, uint32_t count) {
    asm volatile("mbarrier.init.shared.b64 [%0], %1;" :: "r"(mbar), "r"(count) : "memory");
}
__device__ __forceinline__ void mbar_expect_tx(uint32_t mbar, uint32_t bytes) {
    asm volatile("mbarrier.arrive.expect_tx.shared.b64 _, [%0], %1;"
                 :: "r"(mbar), "r"(bytes) : "memory");
}
__device__ __forceinline__ void mbar_wait(uint32_t mbar, uint32_t parity) {
    uint32_t done;
    asm volatile("{\n\t.reg .pred p;\n\t"
                 "mbarrier.try_wait.parity.acquire.cta.shared::cta.b64 p, [%1], %2;\n\t"
                 "selp.b32 %0, 1, 0, p;\n\t}"
                 : "=r"(done) : "r"(mbar), "r"(parity) : "memory");
    if (!done) {
        asm volatile("{\n\t.reg .pred P1;\n\t"
                     "WL_%=:\n\t"
                     "mbarrier.try_wait.parity.acquire.cta.shared::cta.b64 P1, [%0], %1, 0x989680;\n\t"
                     "@P1 bra.uni WD_%=;\n\t"
                     "bra.uni WL_%=;\n\t"
                     "WD_%=:\n\t}"
                     :: "r"(mbar), "r"(parity) : "memory");
    }
}

__device__ __forceinline__ void tma_load_tile(const CUtensorMap* tm, uint32_t dst,
                                              uint32_t mbar, uint32_t tile) {
    const int c0 = (int)(tile & 31u) * FW_TW;       // d offset (elements)
    const int r0 = (int)(tile >> 5) * FW_N;         // flattened row offset
#pragma unroll
    for (int q = 0; q < 4; ++q) {
        asm volatile(
            "cp.async.bulk.tensor.2d.shared::cta.global.tile.mbarrier::complete_tx::bytes "
            "[%0], [%1, {%2, %3}], [%4];"
            :: "r"(dst + q * 16384), "l"(tm), "r"(c0), "r"(r0 + q * 256), "r"(mbar)
            : "memory");
    }
}

__device__ __forceinline__ void tma_store_tile(const CUtensorMap* tm, uint32_t src,
                                               uint32_t tile) {
    const int c0 = (int)(tile & 31u) * FW_TW;
    const int r0 = (int)(tile >> 5) * FW_N;
#pragma unroll
    for (int q = 0; q < 4; ++q) {
        asm volatile(
            "cp.async.bulk.tensor.2d.global.shared::cta.tile.bulk_group "
            "[%0, {%1, %2}], [%3];"
            :: "l"(tm), "r"(c0), "r"(r0 + q * 256), "r"(src + q * 16384)
            : "memory");
    }
    asm volatile("cp.async.bulk.commit_group;" ::: "memory");
}

template <int N_>
__device__ __forceinline__ void tma_store_wait() {
    asm volatile("cp.async.bulk.wait_group %0;" :: "n"(N_) : "memory");
}

// ---------------- kernel ----------------

__global__ __launch_bounds__(FW_THREADS, 1)
void fwht1024_tma(const __grid_constant__ CUtensorMap tin,
                  const __grid_constant__ CUtensorMap tout) {
    extern __shared__ __align__(1024) unsigned char smem[];
    u64t* bufs = reinterpret_cast<u64t*>(smem);   // float2 units

    uint32_t smem_u32;
    asm("{ .reg .u64 t; cvta.to.shared.u64 t, %1; cvt.u32.u64 %0, t; }"
        : "=r"(smem_u32) : "l"(smem));
    const uint32_t mbar = smem_u32 + FW_MBAR_OFF;

    const int tid = threadIdx.x;
    const int dh  = tid & 7;          // float2 column (0..7) within 16-float tile
    const int jt  = tid >> 3;         // 0..31
    const uint32_t jsw = (uint32_t)(jt & 1);   // phase-B load swizzle

    if (tid == 0) {
#pragma unroll
        for (int s = 0; s < FW_NBUF; ++s) mbar_init(mbar + 8 * s, 1);
    }
    __syncthreads();

    const uint32_t stride = gridDim.x;

    // prologue: prefetch tiles t0 -> slot 0 and t0+stride -> slot 1
    if (tid == 0) {
        if (blockIdx.x < FW_NTILES) {
            mbar_expect_tx(mbar, FW_TILE_BYTES);
            tma_load_tile(&tin, smem_u32, mbar, blockIdx.x);
        }
        if (blockIdx.x + stride < FW_NTILES) {
            mbar_expect_tx(mbar + 8, FW_TILE_BYTES);
            tma_load_tile(&tin, smem_u32 + FW_TILE_BYTES, mbar + 8,
                          blockIdx.x + stride);
        }
    }

    uint32_t phases = 0;   // bit s = parity for next wait on slot s
    uint32_t s = 0;

    for (uint32_t t = blockIdx.x; t < FW_NTILES; t += stride) {
        const uint32_t s1 = (s + 1 >= FW_NBUF) ? s + 1 - FW_NBUF : s + 1;
        const uint32_t s2 = (s + 2 >= FW_NBUF) ? s + 2 - FW_NBUF : s + 2;

        // wait for current tile data (issued ~2 iterations ago)
        mbar_wait(mbar + 8 * s, (phases >> s) & 1u);
        phases ^= 1u << s;

        u64t* buf = bufs + s * (FW_TILE_BYTES / 8);
        u64t v[32];

        // ---- phase A: rows 32a + jt, a = 0..31 (linear layout from TMA) ----
#pragma unroll
        for (int a = 0; a < 32; ++a)
            v[a] = buf[256 * a + tid];

#pragma unroll
        for (int h = 1; h < 32; h <<= 1) {
#pragma unroll
            for (int a = 0; a < 32; ++a)
                if ((a & h) == 0) bfly(v[a], v[a | h]);
        }

        // store element (a, b=jt) at swizzled slot (a*32 + (jt^(a&1)))*8 + dh
#pragma unroll
        for (int a = 0; a < 32; ++a)
            buf[(a * 32 + (jt ^ (a & 1))) * 8 + dh] = v[a];

        __syncthreads();

        // ---- phase B: element (a=jt, b=i) from slot (jt*32 + (i^jsw))*8+dh ----
        const uint32_t pb = (uint32_t)(jt * 256 + dh);
#pragma unroll
        for (int i = 0; i < 32; ++i)
            v[i] = buf[pb + (((uint32_t)i ^ jsw) << 3)];

#pragma unroll
        for (int h = 1; h < 32; h <<= 1) {
#pragma unroll
            for (int i = 0; i < 32; ++i)
                if ((i & h) == 0) bfly(v[i], v[i | h]);
        }

        // final: row n = jt*32 + i, linear layout for TMA (2-way STS, accepted)
#pragma unroll
        for (int i = 0; i < 32; ++i)
            buf[pb + ((uint32_t)i << 3)] = v[i];

        // make generic-proxy writes visible to the async proxy, then store
        asm volatile("fence.proxy.async.shared::cta;" ::: "memory");
        __syncthreads();

        if (tid == 0) {
            // store tile t (pending groups after this: {t-1, t})
            tma_store_tile(&tout, smem_u32 + s * FW_TILE_BYTES, t);

            // prefetch tile t+2 into slot s2. Slot s2 was used by tile t-1's
            // store, issued one full iteration ago: wait_group 1 (<=1 pending
            // group, i.e. t-1 done) is a no-op in steady state.
            const uint32_t t2 = t + 2 * stride;
            if (t2 < FW_NTILES) {
                tma_store_wait<1>();
                mbar_expect_tx(mbar + 8 * s2, FW_TILE_BYTES);
                tma_load_tile(&tin, smem_u32 + s2 * FW_TILE_BYTES,
                              mbar + 8 * s2, t2);
            }
        }

        s = s1;
    }

    if (tid == 0) tma_store_wait<0>();   // flush stores before exit
}

// ---------------- host ----------------

typedef CUresult (*EncodeTiledFn)(
    CUtensorMap*, CUtensorMapDataType, cuuint32_t, void*,
    const cuuint64_t*, const cuuint64_t*, const cuuint32_t*, const cuuint32_t*,
    CUtensorMapInterleave, CUtensorMapSwizzle, CUtensorMapL2promotion,
    CUtensorMapFloatOOBfill);

extern "C" void kernel_launch(void* const* d_in, const int* in_sizes, int n_in,
                              void* d_out, int out_size) {
    void* xp = (void*)d_in[0];
    void* yp = d_out;

    void* fn = nullptr;
    cudaDriverEntryPointQueryResult qr;
    cudaGetDriverEntryPoint("cuTensorMapEncodeTiled", &fn, cudaEnableDefault, &qr);
    EncodeTiledFn encode = (EncodeTiledFn)fn;

    cuuint64_t dims[2]    = {FW_D, (cuuint64_t)64 * FW_N};  // {512, 65536}
    cuuint64_t strides[1] = {FW_D * 4};                     // 2048 B per row
    cuuint32_t box[2]     = {FW_TW, 256};
    cuuint32_t es[2]      = {1, 1};

    CUtensorMap tin, tout;
    encode(&tin, CU_TENSOR_MAP_DATA_TYPE_FLOAT32, 2, xp, dims, strides, box, es,
           CU_TENSOR_MAP_INTERLEAVE_NONE, CU_TENSOR_MAP_SWIZZLE_NONE,
           CU_TENSOR_MAP_L2_PROMOTION_L2_128B, CU_TENSOR_MAP_FLOAT_OOB_FILL_NONE);
    encode(&tout, CU_TENSOR_MAP_DATA_TYPE_FLOAT32, 2, yp, dims, strides, box, es,
           CU_TENSOR_MAP_INTERLEAVE_NONE, CU_TENSOR_MAP_SWIZZLE_NONE,
           CU_TENSOR_MAP_L2_PROMOTION_L2_128B, CU_TENSOR_MAP_FLOAT_OOB_FILL_NONE);

    cudaFuncSetAttribute(fwht1024_tma,
                         cudaFuncAttributeMaxDynamicSharedMemorySize,
                         FW_SMEM_BYTES);

    int sms = 148;
    cudaDeviceGetAttribute(&sms, cudaDevAttrMultiProcessorCount, 0);

    fwht1024_tma<<<sms, FW_THREADS, FW_SMEM_BYTES>>>(tin, tout);
}

// round 10
// speedup vs baseline: 1.0242x; 1.0242x over previous
#include <cuda_runtime.h>
#include <cuda.h>
#include <cstdint>

// FWHT n=1024 over x[64,1024,512] f32, single pass, TMA-pipelined.
//
// R10 = R8 (256 threads, 3 x 64KB buffers, persistent 1 CTA/SM, prefetch
// depth 2, prefetch issued at TOP of iteration) with the tile store split
// into 4 independent 16KB commit groups, and the top-of-loop prefetch
// interleaved with their drain: wait_group<3-q> then load quarter q.
// This replaces R8's full-store-drain block (wait_group<0>) with a
// quarter-drain block + overlapped issue.
//
// n = 32*a + b. Phase A: FWHT_32 over a (rows 32a+jt); swizzled smem
// exchange; Phase B: FWHT_32 over b (rows jt*32+b).

#define FW_N 1024
#define FW_D 512
#define FW_TW 16                          // tile width in floats (64 B)
#define FW_THREADS 256
#define FW_NTILES (64 * (FW_D / FW_TW))   // 2048
#define FW_TILE_BYTES (FW_N * FW_TW * 4)  // 65536
#define FW_QTR_BYTES (FW_TILE_BYTES / 4)  // 16384
#define FW_NBUF 3
#define FW_MBAR_OFF (FW_NBUF * FW_TILE_BYTES)
#define FW_SMEM_BYTES (FW_MBAR_OFF + 64)

typedef unsigned long long u64t;

// packed butterfly on a float2-as-u64: (a,b) -> (a+b, a-b)
__device__ __forceinline__ void bfly(u64t& a, u64t& b) {
    u64t s, d;
    asm("add.rn.f32x2 %0, %2, %3;\n\t"
        "sub.rn.f32x2 %1, %2, %3;"
        : "=l"(s), "=l"(d)
        : "l"(a), "l"(b));
    a = s; b = d;
}

__device__ __forceinline__ void mbar_init(uint32_t mbar, uint32_t count) {
    asm volatile("mbarrier.init.shared.b64 [%0], %1;" :: "r"(mbar), "r"(count) : "memory");
}
__device__ __forceinline__ void mbar_expect_tx(uint32_t mbar, uint32_t bytes) {
    asm volatile("mbarrier.arrive.expect_tx.shared.b64 _, [%0], %1;"
                 :: "r"(mbar), "r"(bytes) : "memory");
}
__device__ __forceinline__ void mbar_wait(uint32_t mbar, uint32_t parity) {
    uint32_t done;
    asm volatile("{\n\t.reg .pred p;\n\t"
                 "mbarrier.try_wait.parity.acquire.cta.shared::cta.b64 p, [%1], %2;\n\t"
                 "selp.b32 %0, 1, 0, p;\n\t}"
                 : "=r"(done) : "r"(mbar), "r"(parity) : "memory");
    if (!done) {
        asm volatile("{\n\t.reg .pred P1;\n\t"
                     "WL_%=:\n\t"
                     "mbarrier.try_wait.parity.acquire.cta.shared::cta.b64 P1, [%0], %1, 0x989680;\n\t"
                     "@P1 bra.uni WD_%=;\n\t"
                     "bra.uni WL_%=;\n\t"
                     "WD_%=:\n\t}"
                     :: "r"(mbar), "r"(parity) : "memory");
    }
}

// one 16KB quarter box: rows [r0 + q*256, +256), all FW_TW columns
__device__ __forceinline__ void tma_load_qtr(const CUtensorMap* tm, uint32_t dst,
                                             uint32_t mbar, uint32_t tile, int q) {
    const int c0 = (int)(tile & 31u) * FW_TW;
    const int r0 = (int)(tile >> 5) * FW_N + q * 256;
    asm volatile(
        "cp.async.bulk.tensor.2d.shared::cta.global.tile.mbarrier::complete_tx::bytes "
        "[%0], [%1, {%2, %3}], [%4];"
        :: "r"(dst + (uint32_t)q * FW_QTR_BYTES), "l"(tm), "r"(c0), "r"(r0), "r"(mbar)
        : "memory");
}

__device__ __forceinline__ void tma_load_tile(const CUtensorMap* tm, uint32_t dst,
                                              uint32_t mbar, uint32_t tile) {
#pragma unroll
    for (int q = 0; q < 4; ++q) tma_load_qtr(tm, dst, mbar, tile, q);
}

// store one 16KB quarter as its OWN commit group (4 groups per tile)
__device__ __forceinline__ void tma_store_qtr(const CUtensorMap* tm, uint32_t src,
                                              uint32_t tile, int q) {
    const int c0 = (int)(tile & 31u) * FW_TW;
    const int r0 = (int)(tile >> 5) * FW_N + q * 256;
    asm volatile(
        "cp.async.bulk.tensor.2d.global.shared::cta.tile.bulk_group "
        "[%0, {%1, %2}], [%3];"
        :: "l"(tm), "r"(c0), "r"(r0), "r"(src + (uint32_t)q * FW_QTR_BYTES)
        : "memory");
    asm volatile("cp.async.bulk.commit_group;" ::: "memory");
}

template <int N_>
__device__ __forceinline__ void tma_store_wait() {
    asm volatile("cp.async.bulk.wait_group %0;" :: "n"(N_) : "memory");
}

// ---------------- kernel ----------------

__global__ __launch_bounds__(FW_THREADS, 1)
void fwht1024_tma(const __grid_constant__ CUtensorMap tin,
                  const __grid_constant__ CUtensorMap tout) {
    extern __shared__ __align__(1024) unsigned char smem[];
    u64t* bufs = reinterpret_cast<u64t*>(smem);   // float2 units

    uint32_t smem_u32;
    asm("{ .reg .u64 t; cvta.to.shared.u64 t, %1; cvt.u32.u64 %0, t; }"
        : "=r"(smem_u32) : "l"(smem));
    const uint32_t mbar = smem_u32 + FW_MBAR_OFF;

    const int tid = threadIdx.x;
    const int dh  = tid & 7;          // float2 column (0..7) within 16-float tile
    const int jt  = tid >> 3;         // 0..31
    const uint32_t jsw = (uint32_t)(jt & 1);   // phase-B load swizzle

    if (tid == 0) {
#pragma unroll
        for (int s = 0; s < FW_NBUF; ++s) mbar_init(mbar + 8 * s, 1);
    }
    __syncthreads();

    const uint32_t stride = gridDim.x;

    // prologue: prefetch tiles t0 -> slot 0 and t0+stride -> slot 1
    if (tid == 0) {
        if (blockIdx.x < FW_NTILES) {
            mbar_expect_tx(mbar, FW_TILE_BYTES);
            tma_load_tile(&tin, smem_u32, mbar, blockIdx.x);
        }
        if (blockIdx.x + stride < FW_NTILES) {
            mbar_expect_tx(mbar + 8, FW_TILE_BYTES);
            tma_load_tile(&tin, smem_u32 + FW_TILE_BYTES, mbar + 8,
                          blockIdx.x + stride);
        }
    }

    uint32_t phases = 0;   // bit s = parity for next wait on slot s
    uint32_t s = 0;

    for (uint32_t t = blockIdx.x; t < FW_NTILES; t += stride) {
        const uint32_t s1 = (s + 1 >= FW_NBUF) ? s + 1 - FW_NBUF : s + 1;
        const uint32_t s2 = (s + 2 >= FW_NBUF) ? s + 2 - FW_NBUF : s + 2;

        // prefetch tile t+2 into slot s2, interleaved with the drain of the
        // 4 store quarter-groups of tile t-1 (which wrote from slot s2):
        // wait_group<3-q> guarantees quarters 0..q drained (in-order retire),
        // then quarter q's 16KB region is safe to overwrite.
        const uint32_t t2 = t + 2 * stride;
        if (tid == 0 && t2 < FW_NTILES) {
            const uint32_t dst = smem_u32 + s2 * FW_TILE_BYTES;
            mbar_expect_tx(mbar + 8 * s2, FW_TILE_BYTES);
            tma_store_wait<3>();
            tma_load_qtr(&tin, dst, mbar + 8 * s2, t2, 0);
            tma_store_wait<2>();
            tma_load_qtr(&tin, dst, mbar + 8 * s2, t2, 1);
            tma_store_wait<1>();
            tma_load_qtr(&tin, dst, mbar + 8 * s2, t2, 2);
            tma_store_wait<0>();
            tma_load_qtr(&tin, dst, mbar + 8 * s2, t2, 3);
        }

        // wait for current tile data (issued 2 iterations ago)
        mbar_wait(mbar + 8 * s, (phases >> s) & 1u);
        phases ^= 1u << s;

        u64t* buf = bufs + s * (FW_TILE_BYTES / 8);
        u64t v[32];

        // ---- phase A: rows 32a + jt, a = 0..31 (linear layout from TMA) ----
#pragma unroll
        for (int a = 0; a < 32; ++a)
            v[a] = buf[256 * a + tid];

#pragma unroll
        for (int h = 1; h < 32; h <<= 1) {
#pragma unroll
            for (int a = 0; a < 32; ++a)
                if ((a & h) == 0) bfly(v[a], v[a | h]);
        }

        // store element (a, b=jt) at swizzled slot (a*32 + (jt^(a&1)))*8 + dh
#pragma unroll
        for (int a = 0; a < 32; ++a)
            buf[(a * 32 + (jt ^ (a & 1))) * 8 + dh] = v[a];

        __syncthreads();

        // ---- phase B: element (a=jt, b=i) from slot (jt*32 + (i^jsw))*8+dh ----
        const uint32_t pb = (uint32_t)(jt * 256 + dh);
#pragma unroll
        for (int i = 0; i < 32; ++i)
            v[i] = buf[pb + (((uint32_t)i ^ jsw) << 3)];

#pragma unroll
        for (int h = 1; h < 32; h <<= 1) {
#pragma unroll
            for (int i = 0; i < 32; ++i)
                if ((i & h) == 0) bfly(v[i], v[i | h]);
        }

        // final: row n = jt*32 + i, linear layout for TMA (2-way STS, accepted)
#pragma unroll
        for (int i = 0; i < 32; ++i)
            buf[pb + ((uint32_t)i << 3)] = v[i];

        // make generic-proxy writes visible to the async proxy, then store
        asm volatile("fence.proxy.async.shared::cta;" ::: "memory");
        __syncthreads();

        if (tid == 0) {
            const uint32_t src = smem_u32 + s * FW_TILE_BYTES;
#pragma unroll
            for (int q = 0; q < 4; ++q)
                tma_store_qtr(&tout, src, t, q);
        }

        s = s1;
    }

    if (tid == 0) tma_store_wait<0>();   // flush stores before exit
}

// ---------------- host ----------------

typedef CUresult (*EncodeTiledFn)(
    CUtensorMap*, CUtensorMapDataType, cuuint32_t, void*,
    const cuuint64_t*, const cuuint64_t*, const cuuint32_t*, const cuuint32_t*,
    CUtensorMapInterleave, CUtensorMapSwizzle, CUtensorMapL2promotion,
    CUtensorMapFloatOOBfill);

extern "C" void kernel_launch(void* const* d_in, const int* in_sizes, int n_in,
                              void* d_out, int out_size) {
    void* xp = (void*)d_in[0];
    void* yp = d_out;

    void* fn = nullptr;
    cudaDriverEntryPointQueryResult qr;
    cudaGetDriverEntryPoint("cuTensorMapEncodeTiled", &fn, cudaEnableDefault, &qr);
    EncodeTiledFn encode = (EncodeTiledFn)fn;

    cuuint64_t dims[2]    = {FW_D, (cuuint64_t)64 * FW_N};  // {512, 65536}
    cuuint64_t strides[1] = {FW_D * 4};                     // 2048 B per row
    cuuint32_t box[2]     = {FW_TW, 256};
    cuuint32_t es[2]      = {1, 1};

    CUtensorMap tin, tout;
    encode(&tin, CU_TENSOR_MAP_DATA_TYPE_FLOAT32, 2, xp, dims, strides, box, es,
           CU_TENSOR_MAP_INTERLEAVE_NONE, CU_TENSOR_MAP_SWIZZLE_NONE,
           CU_TENSOR_MAP_L2_PROMOTION_L2_128B, CU_TENSOR_MAP_FLOAT_OOB_FILL_NONE);
    encode(&tout, CU_TENSOR_MAP_DATA_TYPE_FLOAT32, 2, yp, dims, strides, box, es,
           CU_TENSOR_MAP_INTERLEAVE_NONE, CU_TENSOR_MAP_SWIZZLE_NONE,
           CU_TENSOR_MAP_L2_PROMOTION_L2_128B, CU_TENSOR_MAP_FLOAT_OOB_FILL_NONE);

    cudaFuncSetAttribute(fwht1024_tma,
                         cudaFuncAttributeMaxDynamicSharedMemorySize,
                         FW_SMEM_BYTES);

    int sms = 148;
    cudaDeviceGetAttribute(&sms, cudaDevAttrMultiProcessorCount, 0);

    fwht1024_tma<<<sms, FW_THREADS, FW_SMEM_BYTES>>>(tin, tout);
}